// round 10
// baseline (speedup 1.0000x reference)
#include <cuda_runtime.h>

#define NCFG 128
#define VEC  16384
#define NB   8192
#define ETA  0.001f
#define NBLK 512

// Scratch (no allocation allowed)
__device__ float g_vec[NCFG * VEC];   // 8 MB: per-config (bot || top)
__device__ float g_h[NCFG * 64];      // NN hidden layer
__device__ unsigned g_cnt   = 0;      // grid barrier arrivals
__device__ unsigned g_epoch = 0;      // grid barrier generation (monotonic)

union Smem {
    struct { float s[4][256]; int p[4]; } p1;
    struct { float sH[128][66]; float sW[64][32]; } p2;             // 41984 B
    struct { float sbot[1024], stop[1024], T[1024]; float vbuf[2][256]; } p3;
};

// Sense-free grid barrier: epoch is monotonic across graph replays; count
// resets each pass. Safe: all NBLK blocks co-resident (4 blocks/SM via
// launch_bounds(256,4): 64 regs, 42KB smem -> capacity 148*4=592 >= 512).
__device__ __forceinline__ void grid_barrier() {
    __syncthreads();
    if (threadIdx.x == 0) {
        __threadfence();
        volatile unsigned* ep = &g_epoch;
        unsigned base = *ep;                 // stable: no bump before all arrive
        unsigned old = atomicAdd(&g_cnt, 1);
        if (old == NBLK - 1) {
            g_cnt = 0;                       // reset for next barrier
            __threadfence();
            atomicAdd(&g_epoch, 1);          // release
        } else {
            while (*ep == base) __nanosleep(32);
        }
        __threadfence();
    }
    __syncthreads();
}

__global__ void __launch_bounds__(256, 4)
k_fused(const int* __restrict__ cfg,
        const float* __restrict__ A,
        const float* __restrict__ W1,
        const float* __restrict__ b1,
        const float* __restrict__ W2,
        const float* __restrict__ b2,
        float* __restrict__ out)
{
    __shared__ Smem sm;
    const int blk = blockIdx.x;
    const int tid = threadIdx.x;   // 256

    // ================= Phase 1: base tensors + eta*b2, and h =================
    // 1024 (config, x) tiles, 2 per block.
    #pragma unroll 1
    for (int ti = 0; ti < 2; ti++) {
        const int tile = blk * 2 + ti;
        const int b = tile >> 3, x = tile & 7;

        if (tid < 4) sm.p1.p[tid] = cfg[b * 32 + x * 4 + tid];
        __syncthreads();

        #pragma unroll
        for (int t = 0; t < 4; t++) {
            int n = tid + t * 256;
            int y = n >> 8, q = n & 255;
            float2 a2 = ((const float2*)A)[(x * 4 + y) * 256 + q];
            sm.p1.s[y][q] = sm.p1.p[y] ? a2.y : a2.x;
        }
        __syncthreads();

        float* vout = g_vec + b * VEC;
        const int n0 = tid * 4;
        const int i = n0 >> 6, j = (n0 >> 2) & 15;
        const int l = i >> 2, L = i & 3, r = j >> 2, R = j & 3;

        // bot quad: bot[i,j,U] = sum_u s0[l,r,u] * s1[L,R,u*4+U]
        {
            float4 acc = make_float4(0.f, 0.f, 0.f, 0.f);
            #pragma unroll
            for (int u = 0; u < 4; u++) {
                float a = sm.p1.s[0][l * 64 + r * 16 + u];
                float4 w = *(const float4*)&sm.p1.s[1][L * 64 + R * 16 + u * 4];
                acc.x = fmaf(a, w.x, acc.x); acc.y = fmaf(a, w.y, acc.y);
                acc.z = fmaf(a, w.z, acc.z); acc.w = fmaf(a, w.w, acc.w);
            }
            float4 bb = *(const float4*)&b2[x * 1024 + n0];
            acc.x = fmaf(ETA, bb.x, acc.x); acc.y = fmaf(ETA, bb.y, acc.y);
            acc.z = fmaf(ETA, bb.z, acc.z); acc.w = fmaf(ETA, bb.w, acc.w);
            *(float4*)&vout[x * 1024 + n0] = acc;
        }
        // top quad: top[i,j,d] = sum_u s2[l,r,d*4+u] * s3[L,R,u*4]
        {
            float w0 = sm.p1.s[3][L * 64 + R * 16 + 0];
            float w1 = sm.p1.s[3][L * 64 + R * 16 + 4];
            float w2 = sm.p1.s[3][L * 64 + R * 16 + 8];
            float w3 = sm.p1.s[3][L * 64 + R * 16 + 12];
            float4 acc;
            #pragma unroll
            for (int d = 0; d < 4; d++) {
                float4 v = *(const float4*)&sm.p1.s[2][l * 64 + r * 16 + d * 4];
                ((float*)&acc)[d] = fmaf(v.x, w0, fmaf(v.y, w1, fmaf(v.z, w2, v.w * w3)));
            }
            float4 bb = *(const float4*)&b2[NB + x * 1024 + n0];
            acc.x = fmaf(ETA, bb.x, acc.x); acc.y = fmaf(ETA, bb.y, acc.y);
            acc.z = fmaf(ETA, bb.z, acc.z); acc.w = fmaf(ETA, bb.w, acc.w);
            *(float4*)&vout[NB + x * 1024 + n0] = acc;
        }
        __syncthreads();
    }

    // h[blk] = relu(cfg[blk] @ W1 + b1), one config per block (blk < 128)
    if (blk < NCFG && tid < 64) {
        float acc = b1[tid];
        #pragma unroll
        for (int ii = 0; ii < 32; ii++)
            acc = fmaf((float)cfg[blk * 32 + ii], W1[ii * 64 + tid], acc);
        g_h[blk * 64 + tid] = fmaxf(acc, 0.f);
    }

    grid_barrier();

    // ================= Phase 2: g_vec += ETA * (H @ W2), FFMA2 ===============
    // 512 col-tiles of 32 cols; exactly one per block. W2 read once chip-wide.
    {
        const int colBase = blk * 32;
        for (int n = tid; n < 8192; n += 256)
            sm.p2.sH[n >> 6][n & 63] = g_h[n];      // [row][k], pad 66
        for (int n = tid; n < 2048; n += 256)
            sm.p2.sW[n >> 5][n & 31] = W2[(n >> 5) * 16384 + colBase + (n & 31)];
        __syncthreads();

        const int rb = tid >> 3;   // rows rb*4 .. rb*4+3
        const int cb = tid & 7;    // cols cb*4 .. cb*4+3 (2 f32x2 pairs)

        unsigned long long acc[4][2];
        #pragma unroll
        for (int i = 0; i < 4; i++) { acc[i][0] = 0ull; acc[i][1] = 0ull; }

        #pragma unroll 8
        for (int k = 0; k < 64; k++) {
            unsigned long long h[4], w[2];
            #pragma unroll
            for (int i = 0; i < 4; i++) {
                float hv = sm.p2.sH[rb * 4 + i][k];
                asm("mov.b64 %0, {%1, %2};" : "=l"(h[i]) : "f"(hv), "f"(hv));
            }
            w[0] = *(const unsigned long long*)&sm.p2.sW[k][cb * 4 + 0];
            w[1] = *(const unsigned long long*)&sm.p2.sW[k][cb * 4 + 2];
            #pragma unroll
            for (int i = 0; i < 4; i++) {
                asm("fma.rn.f32x2 %0, %1, %2, %0;" : "+l"(acc[i][0]) : "l"(h[i]), "l"(w[0]));
                asm("fma.rn.f32x2 %0, %1, %2, %0;" : "+l"(acc[i][1]) : "l"(h[i]), "l"(w[1]));
            }
        }

        #pragma unroll
        for (int i = 0; i < 4; i++) {
            unsigned row = rb * 4 + i;
            #pragma unroll
            for (int j = 0; j < 2; j++) {
                float2* dst = (float2*)&g_vec[row * VEC + colBase + cb * 4 + 2 * j];
                float2 old = *dst;
                float2 v = *(float2*)&acc[i][j];
                old.x = fmaf(ETA, v.x, old.x);
                old.y = fmaf(ETA, v.y, old.y);
                *dst = old;
            }
        }
    }

    grid_barrier();

    // ================= Phase 3: transfer-matrix chain (blk < 128) ============
    if (blk < NCFG) {
        const int b = blk;
        const float* vb = g_vec + b * VEC;

        sm.p3.vbuf[0][tid] = (tid == 0) ? 1.f : 0.f;

        float4 pb = *(const float4*)&vb[tid * 4];
        float4 pt = *(const float4*)&vb[NB + tid * 4];

        int cur = 0;
        #pragma unroll 1
        for (int x = 0; x < 8; x++) {
            __syncthreads();
            *(float4*)&sm.p3.sbot[tid * 4] = pb;
            *(float4*)&sm.p3.stop[tid * 4] = pt;
            __syncthreads();

            if (x < 7) {
                pb = *(const float4*)&vb[(x + 1) * 1024 + tid * 4];
                pt = *(const float4*)&vb[NB + (x + 1) * 1024 + tid * 4];
            }

            // T[i,J,u] quad
            {
                const int n0 = tid * 4;
                const int i = n0 >> 6, J = (n0 >> 2) & 15;
                float4 acc = make_float4(0.f, 0.f, 0.f, 0.f);
                #pragma unroll
                for (int I = 0; I < 16; I++) {
                    float vv = sm.p3.vbuf[cur][i * 16 + I];
                    float4 tp = *(const float4*)&sm.p3.stop[I * 64 + J * 4];
                    acc.x = fmaf(vv, tp.x, acc.x); acc.y = fmaf(vv, tp.y, acc.y);
                    acc.z = fmaf(vv, tp.z, acc.z); acc.w = fmaf(vv, tp.w, acc.w);
                }
                *(float4*)&sm.p3.T[n0] = acc;
            }
            __syncthreads();

            // vnew[j,J]
            {
                const int j = tid >> 4, J = tid & 15;
                float acc = 0.f;
                #pragma unroll
                for (int i = 0; i < 16; i++) {
                    float4 bo = *(const float4*)&sm.p3.sbot[i * 64 + j * 4];
                    float4 tt = *(const float4*)&sm.p3.T[i * 64 + J * 4];
                    acc = fmaf(bo.x, tt.x, acc);
                    acc = fmaf(bo.y, tt.y, acc);
                    acc = fmaf(bo.z, tt.z, acc);
                    acc = fmaf(bo.w, tt.w, acc);
                }
                sm.p3.vbuf[cur ^ 1][tid] = acc;
            }
            cur ^= 1;
        }
        __syncthreads();
        if (tid == 0) out[b] = sm.p3.vbuf[cur][0];
    }
}

// ---------------------------------------------------------------------------
extern "C" void kernel_launch(void* const* d_in, const int* in_sizes, int n_in,
                              void* d_out, int out_size)
{
    const int*   cfg = (const int*)  d_in[0];
    const float* A   = (const float*)d_in[1];
    const float* W1  = (const float*)d_in[2];
    const float* b1  = (const float*)d_in[3];
    const float* W2  = (const float*)d_in[4];
    const float* b2  = (const float*)d_in[5];
    float* out = (float*)d_out;

    k_fused<<<NBLK, 256>>>(cfg, A, W1, b1, W2, b2, out);
}

// round 12
// speedup vs baseline: 1.1231x; 1.1231x over previous
#include <cuda_runtime.h>

#define NCFG 128
#define VEC  16384
#define NB   8192
#define ETA  0.001f
#define NBLK 256

// Scratch (no allocation allowed)
__device__ float g_vec[NCFG * VEC];   // 8 MB: per-config (bot || top)
__device__ float g_h[NCFG * 64];      // NN hidden layer
__device__ unsigned g_cnt   = 0;      // grid barrier arrivals
__device__ unsigned g_epoch = 0;      // grid barrier generation (monotonic)

union Smem {
    struct { float s[4][256]; } p1;
    struct { float sHT[64][130]; float sW[32][64]; } p2;   // 33280+8192 = 41472 B
    struct { float sbot[1024], stop[1024], T[1024]; float vbuf[2][256]; } p3;
};

// Sense-free grid barrier: epoch monotonic across graph replays; count resets
// each pass. Safe: all NBLK=256 blocks co-resident (2 blocks/SM, 148 SMs).
__device__ __forceinline__ void grid_barrier() {
    __syncthreads();
    if (threadIdx.x == 0) {
        __threadfence();
        volatile unsigned* ep = &g_epoch;
        unsigned base = *ep;
        unsigned old = atomicAdd(&g_cnt, 1);
        if (old == NBLK - 1) {
            g_cnt = 0;
            __threadfence();
            atomicAdd(&g_epoch, 1);
        } else {
            while (*ep == base) __nanosleep(32);
        }
        __threadfence();
    }
    __syncthreads();
}

__global__ void __launch_bounds__(256, 2)
k_fused(const int* __restrict__ cfg,
        const float* __restrict__ A,
        const float* __restrict__ W1,
        const float* __restrict__ b1,
        const float* __restrict__ W2,
        const float* __restrict__ b2,
        float* __restrict__ out)
{
    __shared__ Smem sm;
    const int blk = blockIdx.x;
    const int tid = threadIdx.x;   // 256

    // ================= Phase 1: base tensors + eta*b2, and h =================
    // 1024 (config, x) tiles, 4 per block. A-slices + cfg prefetched into
    // registers one tile ahead; phys-select done per-thread (no smem p[]).
    {
        float2 pa[4];
        int    py[4];
        {   // prefetch tile 0
            const int tile = blk * 4;
            const int b0 = tile >> 3, x0 = tile & 7;
            #pragma unroll
            for (int t = 0; t < 4; t++) {
                int n = tid + t * 256;
                int y = n >> 8, q = n & 255;
                pa[t] = ((const float2*)A)[(x0 * 4 + y) * 256 + q];
                py[t] = cfg[b0 * 32 + x0 * 4 + y];
            }
        }

        #pragma unroll 1
        for (int ti = 0; ti < 4; ti++) {
            const int tile = blk * 4 + ti;
            const int b = tile >> 3, x = tile & 7;

            __syncthreads();   // previous tile's smem reads done
            #pragma unroll
            for (int t = 0; t < 4; t++) {
                int n = tid + t * 256;
                sm.p1.s[n >> 8][n & 255] = py[t] ? pa[t].y : pa[t].x;
            }
            __syncthreads();

            if (ti < 3) {      // prefetch next tile (overlaps compute)
                const int tile2 = tile + 1;
                const int b2i = tile2 >> 3, x2 = tile2 & 7;
                #pragma unroll
                for (int t = 0; t < 4; t++) {
                    int n = tid + t * 256;
                    int y = n >> 8, q = n & 255;
                    pa[t] = ((const float2*)A)[(x2 * 4 + y) * 256 + q];
                    py[t] = cfg[b2i * 32 + x2 * 4 + y];
                }
            }

            float* vout = g_vec + b * VEC;
            const int n0 = tid * 4;
            const int i = n0 >> 6, j = (n0 >> 2) & 15;
            const int l = i >> 2, L = i & 3, r = j >> 2, R = j & 3;

            // bot quad: bot[i,j,U] = sum_u s0[l,r,u] * s1[L,R,u*4+U]
            {
                float4 acc = make_float4(0.f, 0.f, 0.f, 0.f);
                #pragma unroll
                for (int u = 0; u < 4; u++) {
                    float a = sm.p1.s[0][l * 64 + r * 16 + u];
                    float4 w = *(const float4*)&sm.p1.s[1][L * 64 + R * 16 + u * 4];
                    acc.x = fmaf(a, w.x, acc.x); acc.y = fmaf(a, w.y, acc.y);
                    acc.z = fmaf(a, w.z, acc.z); acc.w = fmaf(a, w.w, acc.w);
                }
                float4 bb = *(const float4*)&b2[x * 1024 + n0];
                acc.x = fmaf(ETA, bb.x, acc.x); acc.y = fmaf(ETA, bb.y, acc.y);
                acc.z = fmaf(ETA, bb.z, acc.z); acc.w = fmaf(ETA, bb.w, acc.w);
                *(float4*)&vout[x * 1024 + n0] = acc;
            }
            // top quad: top[i,j,d] = sum_u s2[l,r,d*4+u] * s3[L,R,u*4]
            {
                float w0 = sm.p1.s[3][L * 64 + R * 16 + 0];
                float w1 = sm.p1.s[3][L * 64 + R * 16 + 4];
                float w2 = sm.p1.s[3][L * 64 + R * 16 + 8];
                float w3 = sm.p1.s[3][L * 64 + R * 16 + 12];
                float4 acc;
                #pragma unroll
                for (int d = 0; d < 4; d++) {
                    float4 v = *(const float4*)&sm.p1.s[2][l * 64 + r * 16 + d * 4];
                    ((float*)&acc)[d] = fmaf(v.x, w0, fmaf(v.y, w1, fmaf(v.z, w2, v.w * w3)));
                }
                float4 bb = *(const float4*)&b2[NB + x * 1024 + n0];
                acc.x = fmaf(ETA, bb.x, acc.x); acc.y = fmaf(ETA, bb.y, acc.y);
                acc.z = fmaf(ETA, bb.z, acc.z); acc.w = fmaf(ETA, bb.w, acc.w);
                *(float4*)&vout[NB + x * 1024 + n0] = acc;
            }
        }
    }

    // h[blk] = relu(cfg[blk] @ W1 + b1), one config per block (blk < 128)
    if (blk < NCFG && tid < 64) {
        float acc = b1[tid];
        #pragma unroll
        for (int ii = 0; ii < 32; ii++)
            acc = fmaf((float)cfg[blk * 32 + ii], W1[ii * 64 + tid], acc);
        g_h[blk * 64 + tid] = fmaxf(acc, 0.f);
    }

    grid_barrier();

    // ====== Phase 2: g_vec += ETA * (H @ W2), FFMA2 row-pair packing ========
    // 256 col-tiles of 64 cols; one per block. W2 read once chip-wide.
    // Microtile: 8 rows (4 f32x2 row-pairs) x 4 cols. H pairs via LDS.64
    // from transposed sHT (no dup-movs on H); W staged in two 32-k chunks.
    {
        const int colBase = blk * 64;

        for (int n = tid; n < 8192; n += 256) {
            int r = n >> 6, k = n & 63;
            sm.p2.sHT[k][r] = g_h[n];          // coalesced read; 2-way-conflict store
        }

        const int rb = tid >> 4;   // 0..15 -> rows rb*8 .. rb*8+7
        const int cb = tid & 15;   // 0..15 -> cols cb*4 .. cb*4+3

        unsigned long long acc[4][4];  // [row-pair][col], lanes = rows (2p, 2p+1)
        #pragma unroll
        for (int p = 0; p < 4; p++)
            #pragma unroll
            for (int j = 0; j < 4; j++) acc[p][j] = 0ull;

        #pragma unroll 1
        for (int ks = 0; ks < 64; ks += 32) {
            __syncthreads();   // also orders sHT fill before first read
            for (int n = tid; n < 2048; n += 256)
                sm.p2.sW[n >> 6][n & 63] =
                    W2[(ks + (n >> 6)) * 16384 + colBase + (n & 63)];
            __syncthreads();

            #pragma unroll 8
            for (int kk = 0; kk < 32; kk++) {
                const int k = ks + kk;
                unsigned long long h[4], w[4];
                #pragma unroll
                for (int p = 0; p < 4; p++)
                    h[p] = *(const unsigned long long*)&sm.p2.sHT[k][rb * 8 + 2 * p];
                #pragma unroll
                for (int j = 0; j < 4; j++) {
                    float wv = sm.p2.sW[kk][cb * 4 + j];
                    asm("mov.b64 %0, {%1, %2};" : "=l"(w[j]) : "f"(wv), "f"(wv));
                }
                #pragma unroll
                for (int p = 0; p < 4; p++)
                    #pragma unroll
                    for (int j = 0; j < 4; j++)
                        asm("fma.rn.f32x2 %0, %1, %2, %0;"
                            : "+l"(acc[p][j]) : "l"(h[p]), "l"(w[j]));
            }
        }

        #pragma unroll
        for (int p = 0; p < 4; p++) {
            unsigned r0 = rb * 8 + 2 * p;
            #pragma unroll
            for (int j = 0; j < 4; j++) {
                float2 v = *(float2*)&acc[p][j];
                unsigned col = colBase + cb * 4 + j;
                float* d0 = &g_vec[r0 * VEC + col];
                float* d1 = &g_vec[(r0 + 1) * VEC + col];
                *d0 = fmaf(ETA, v.x, *d0);
                *d1 = fmaf(ETA, v.y, *d1);
            }
        }
    }

    grid_barrier();

    // ================= Phase 3: transfer-matrix chain (blk < 128) ============
    if (blk < NCFG) {
        const int b = blk;
        const float* vb = g_vec + b * VEC;

        sm.p3.vbuf[0][tid] = (tid == 0) ? 1.f : 0.f;

        float4 pb = *(const float4*)&vb[tid * 4];
        float4 pt = *(const float4*)&vb[NB + tid * 4];

        int cur = 0;
        #pragma unroll 1
        for (int x = 0; x < 8; x++) {
            __syncthreads();
            *(float4*)&sm.p3.sbot[tid * 4] = pb;
            *(float4*)&sm.p3.stop[tid * 4] = pt;
            __syncthreads();

            if (x < 7) {
                pb = *(const float4*)&vb[(x + 1) * 1024 + tid * 4];
                pt = *(const float4*)&vb[NB + (x + 1) * 1024 + tid * 4];
            }

            // T[i,J,u] quad
            {
                const int n0 = tid * 4;
                const int i = n0 >> 6, J = (n0 >> 2) & 15;
                float4 acc = make_float4(0.f, 0.f, 0.f, 0.f);
                #pragma unroll
                for (int I = 0; I < 16; I++) {
                    float vv = sm.p3.vbuf[cur][i * 16 + I];
                    float4 tp = *(const float4*)&sm.p3.stop[I * 64 + J * 4];
                    acc.x = fmaf(vv, tp.x, acc.x); acc.y = fmaf(vv, tp.y, acc.y);
                    acc.z = fmaf(vv, tp.z, acc.z); acc.w = fmaf(vv, tp.w, acc.w);
                }
                *(float4*)&sm.p3.T[n0] = acc;
            }
            __syncthreads();

            // vnew[j,J]
            {
                const int j = tid >> 4, J = tid & 15;
                float acc = 0.f;
                #pragma unroll
                for (int i = 0; i < 16; i++) {
                    float4 bo = *(const float4*)&sm.p3.sbot[i * 64 + j * 4];
                    float4 tt = *(const float4*)&sm.p3.T[i * 64 + J * 4];
                    acc = fmaf(bo.x, tt.x, acc);
                    acc = fmaf(bo.y, tt.y, acc);
                    acc = fmaf(bo.z, tt.z, acc);
                    acc = fmaf(bo.w, tt.w, acc);
                }
                sm.p3.vbuf[cur ^ 1][tid] = acc;
            }
            cur ^= 1;
        }
        __syncthreads();
        if (tid == 0) out[b] = sm.p3.vbuf[cur][0];
    }
}

// ---------------------------------------------------------------------------
extern "C" void kernel_launch(void* const* d_in, const int* in_sizes, int n_in,
                              void* d_out, int out_size)
{
    const int*   cfg = (const int*)  d_in[0];
    const float* A   = (const float*)d_in[1];
    const float* W1  = (const float*)d_in[2];
    const float* b1  = (const float*)d_in[3];
    const float* W2  = (const float*)d_in[4];
    const float* b2  = (const float*)d_in[5];
    float* out = (float*)d_out;

    k_fused<<<NBLK, 256>>>(cfg, A, W1, b1, W2, b2, out);
}

// round 13
// speedup vs baseline: 1.1967x; 1.0656x over previous
#include <cuda_runtime.h>

#define NCFG 128
#define VEC  16384
#define NB   8192
#define ETA  0.001f
#define NBLK 256

// Scratch (no allocation allowed)
__device__ float g_vec[NCFG * VEC];    // 8 MB: per-config base (bot || top)
__device__ float g_corr[NCFG * VEC];   // 8 MB: ETA * (H @ W2)
__device__ float g_h[NCFG * 64];       // NN hidden layer
__device__ unsigned g_cnt   = 0;
__device__ unsigned g_epoch = 0;

union Smem {
    struct { float s[4][256]; int p[4]; } p1;
    struct { float sH[128][66]; float sW[64][32]; } p2;             // 41984 B
    struct { float sbot[1024], stop[1024], T[1024]; float vbuf[2][256]; } p3;
};

// Sense-free grid barrier: epoch monotonic across graph replays; count resets
// each pass. Safe: all NBLK=256 blocks co-resident (2 blocks/SM, 148 SMs).
__device__ __forceinline__ void grid_barrier() {
    __syncthreads();
    if (threadIdx.x == 0) {
        __threadfence();
        volatile unsigned* ep = &g_epoch;
        unsigned base = *ep;
        unsigned old = atomicAdd(&g_cnt, 1);
        if (old == NBLK - 1) {
            g_cnt = 0;
            __threadfence();
            atomicAdd(&g_epoch, 1);
        } else {
            while (*ep == base) __nanosleep(32);
        }
        __threadfence();
    }
    __syncthreads();
}

__global__ void __launch_bounds__(256, 2)
k_fused(const int* __restrict__ cfg,
        const float* __restrict__ A,
        const float* __restrict__ W1,
        const float* __restrict__ b1,
        const float* __restrict__ W2,
        const float* __restrict__ b2,
        float* __restrict__ out)
{
    __shared__ Smem sm;
    const int blk = blockIdx.x;
    const int tid = threadIdx.x;   // 256

    // ======== Step A: h[blk] = relu(cfg[blk] @ W1 + b1)  (blk < 128) =========
    // Tiny: all blocks reach barrier-1 nearly simultaneously (no skew).
    if (blk < NCFG && tid < 64) {
        float acc = b1[tid];
        #pragma unroll
        for (int ii = 0; ii < 32; ii++)
            acc = fmaf((float)cfg[blk * 32 + ii], W1[ii * 64 + tid], acc);
        g_h[blk * 64 + tid] = fmaxf(acc, 0.f);
    }

    grid_barrier();   // protects only g_h (32 KB)

    // ======== Step B: g_corr = ETA * (H @ W2), FFMA2 (pure stores) ===========
    // 512 col-tiles of 32 cols; each block does tiles blk and blk+256.
    // W2 read exactly once chip-wide.
    for (int n = tid; n < 8192; n += 256)
        sm.p2.sH[n >> 6][n & 63] = g_h[n];      // [row][k], pad 66

    #pragma unroll 1
    for (int t = blk; t < 512; t += NBLK) {
        const int colBase = t * 32;
        __syncthreads();
        for (int n = tid; n < 2048; n += 256)
            sm.p2.sW[n >> 5][n & 31] = W2[(n >> 5) * 16384 + colBase + (n & 31)];
        __syncthreads();

        const int rb = tid >> 3;   // rows rb*4 .. rb*4+3
        const int cb = tid & 7;    // cols cb*4 .. cb*4+3 (2 f32x2 pairs)

        unsigned long long acc[4][2];
        #pragma unroll
        for (int i = 0; i < 4; i++) { acc[i][0] = 0ull; acc[i][1] = 0ull; }

        #pragma unroll 8
        for (int k = 0; k < 64; k++) {
            unsigned long long h[4], w[2];
            #pragma unroll
            for (int i = 0; i < 4; i++) {
                float hv = sm.p2.sH[rb * 4 + i][k];
                asm("mov.b64 %0, {%1, %2};" : "=l"(h[i]) : "f"(hv), "f"(hv));
            }
            w[0] = *(const unsigned long long*)&sm.p2.sW[k][cb * 4 + 0];
            w[1] = *(const unsigned long long*)&sm.p2.sW[k][cb * 4 + 2];
            #pragma unroll
            for (int i = 0; i < 4; i++) {
                asm("fma.rn.f32x2 %0, %1, %2, %0;" : "+l"(acc[i][0]) : "l"(h[i]), "l"(w[0]));
                asm("fma.rn.f32x2 %0, %1, %2, %0;" : "+l"(acc[i][1]) : "l"(h[i]), "l"(w[1]));
            }
        }

        #pragma unroll
        for (int i = 0; i < 4; i++) {
            unsigned row = rb * 4 + i;
            #pragma unroll
            for (int j = 0; j < 2; j++) {
                float2 v = *(float2*)&acc[i][j];
                v.x *= ETA; v.y *= ETA;
                *(float2*)&g_corr[row * VEC + colBase + cb * 4 + 2 * j] = v;
            }
        }
    }

    __syncthreads();   // smem union transition (p2 -> p1)

    // ======== Step C: base tensors + eta*b2 -> g_vec (no barrier needed) =====
    // 1024 (config, x) tiles, 4 per block. Absorbs any Step-B straggler skew.
    #pragma unroll 1
    for (int ti = 0; ti < 4; ti++) {
        const int tile = blk * 4 + ti;
        const int b = tile >> 3, x = tile & 7;

        if (tid < 4) sm.p1.p[tid] = cfg[b * 32 + x * 4 + tid];
        __syncthreads();

        #pragma unroll
        for (int t = 0; t < 4; t++) {
            int n = tid + t * 256;
            int y = n >> 8, q = n & 255;
            float2 a2 = ((const float2*)A)[(x * 4 + y) * 256 + q];
            sm.p1.s[y][q] = sm.p1.p[y] ? a2.y : a2.x;
        }
        __syncthreads();

        float* vout = g_vec + b * VEC;
        const int n0 = tid * 4;
        const int i = n0 >> 6, j = (n0 >> 2) & 15;
        const int l = i >> 2, L = i & 3, r = j >> 2, R = j & 3;

        // bot quad: bot[i,j,U] = sum_u s0[l,r,u] * s1[L,R,u*4+U]
        {
            float4 acc = make_float4(0.f, 0.f, 0.f, 0.f);
            #pragma unroll
            for (int u = 0; u < 4; u++) {
                float a = sm.p1.s[0][l * 64 + r * 16 + u];
                float4 w = *(const float4*)&sm.p1.s[1][L * 64 + R * 16 + u * 4];
                acc.x = fmaf(a, w.x, acc.x); acc.y = fmaf(a, w.y, acc.y);
                acc.z = fmaf(a, w.z, acc.z); acc.w = fmaf(a, w.w, acc.w);
            }
            float4 bb = *(const float4*)&b2[x * 1024 + n0];
            acc.x = fmaf(ETA, bb.x, acc.x); acc.y = fmaf(ETA, bb.y, acc.y);
            acc.z = fmaf(ETA, bb.z, acc.z); acc.w = fmaf(ETA, bb.w, acc.w);
            *(float4*)&vout[x * 1024 + n0] = acc;
        }
        // top quad: top[i,j,d] = sum_u s2[l,r,d*4+u] * s3[L,R,u*4]
        {
            float w0 = sm.p1.s[3][L * 64 + R * 16 + 0];
            float w1 = sm.p1.s[3][L * 64 + R * 16 + 4];
            float w2 = sm.p1.s[3][L * 64 + R * 16 + 8];
            float w3 = sm.p1.s[3][L * 64 + R * 16 + 12];
            float4 acc;
            #pragma unroll
            for (int d = 0; d < 4; d++) {
                float4 v = *(const float4*)&sm.p1.s[2][l * 64 + r * 16 + d * 4];
                ((float*)&acc)[d] = fmaf(v.x, w0, fmaf(v.y, w1, fmaf(v.z, w2, v.w * w3)));
            }
            float4 bb = *(const float4*)&b2[NB + x * 1024 + n0];
            acc.x = fmaf(ETA, bb.x, acc.x); acc.y = fmaf(ETA, bb.y, acc.y);
            acc.z = fmaf(ETA, bb.z, acc.z); acc.w = fmaf(ETA, bb.w, acc.w);
            *(float4*)&vout[NB + x * 1024 + n0] = acc;
        }
        __syncthreads();
    }

    grid_barrier();   // protects g_vec + g_corr

    // ======== Step D: transfer-matrix chain (blk < 128), vec = base + corr ===
    if (blk < NCFG) {
        const int b = blk;
        const float* vb = g_vec + b * VEC;
        const float* vc = g_corr + b * VEC;

        sm.p3.vbuf[0][tid] = (tid == 0) ? 1.f : 0.f;

        float4 pb, pt;
        {
            float4 b0 = *(const float4*)&vb[tid * 4];
            float4 c0 = *(const float4*)&vc[tid * 4];
            pb = make_float4(b0.x + c0.x, b0.y + c0.y, b0.z + c0.z, b0.w + c0.w);
            float4 b1_ = *(const float4*)&vb[NB + tid * 4];
            float4 c1 = *(const float4*)&vc[NB + tid * 4];
            pt = make_float4(b1_.x + c1.x, b1_.y + c1.y, b1_.z + c1.z, b1_.w + c1.w);
        }

        int cur = 0;
        #pragma unroll 1
        for (int x = 0; x < 8; x++) {
            __syncthreads();
            *(float4*)&sm.p3.sbot[tid * 4] = pb;
            *(float4*)&sm.p3.stop[tid * 4] = pt;
            __syncthreads();

            if (x < 7) {
                float4 b0 = *(const float4*)&vb[(x + 1) * 1024 + tid * 4];
                float4 c0 = *(const float4*)&vc[(x + 1) * 1024 + tid * 4];
                pb = make_float4(b0.x + c0.x, b0.y + c0.y, b0.z + c0.z, b0.w + c0.w);
                float4 b1_ = *(const float4*)&vb[NB + (x + 1) * 1024 + tid * 4];
                float4 c1 = *(const float4*)&vc[NB + (x + 1) * 1024 + tid * 4];
                pt = make_float4(b1_.x + c1.x, b1_.y + c1.y, b1_.z + c1.z, b1_.w + c1.w);
            }

            // T[i,J,u] quad
            {
                const int n0 = tid * 4;
                const int i = n0 >> 6, J = (n0 >> 2) & 15;
                float4 acc = make_float4(0.f, 0.f, 0.f, 0.f);
                #pragma unroll
                for (int I = 0; I < 16; I++) {
                    float vv = sm.p3.vbuf[cur][i * 16 + I];
                    float4 tp = *(const float4*)&sm.p3.stop[I * 64 + J * 4];
                    acc.x = fmaf(vv, tp.x, acc.x); acc.y = fmaf(vv, tp.y, acc.y);
                    acc.z = fmaf(vv, tp.z, acc.z); acc.w = fmaf(vv, tp.w, acc.w);
                }
                *(float4*)&sm.p3.T[n0] = acc;
            }
            __syncthreads();

            // vnew[j,J]
            {
                const int j = tid >> 4, J = tid & 15;
                float acc = 0.f;
                #pragma unroll
                for (int i = 0; i < 16; i++) {
                    float4 bo = *(const float4*)&sm.p3.sbot[i * 64 + j * 4];
                    float4 tt = *(const float4*)&sm.p3.T[i * 64 + J * 4];
                    acc = fmaf(bo.x, tt.x, acc);
                    acc = fmaf(bo.y, tt.y, acc);
                    acc = fmaf(bo.z, tt.z, acc);
                    acc = fmaf(bo.w, tt.w, acc);
                }
                sm.p3.vbuf[cur ^ 1][tid] = acc;
            }
            cur ^= 1;
        }
        __syncthreads();
        if (tid == 0) out[b] = sm.p3.vbuf[cur][0];
    }
}

// ---------------------------------------------------------------------------
extern "C" void kernel_launch(void* const* d_in, const int* in_sizes, int n_in,
                              void* d_out, int out_size)
{
    const int*   cfg = (const int*)  d_in[0];
    const float* A   = (const float*)d_in[1];
    const float* W1  = (const float*)d_in[2];
    const float* b1  = (const float*)d_in[3];
    const float* W2  = (const float*)d_in[4];
    const float* b2  = (const float*)d_in[5];
    float* out = (float*)d_out;

    k_fused<<<NBLK, 256>>>(cfg, A, W1, b1, W2, b2, out);
}